// round 15
// baseline (speedup 1.0000x reference)
#include <cuda_runtime.h>
#include <cuda_fp16.h>
#include <cstdint>
#include <math.h>

#define T_TOK 2048
#define DIM 1024
#define HID 4096
#define NE 8
#define MAXMT 40
#define SWZ(o) ((o) ^ (((o) >> 3) & 0x70))
#define STAGE 32768
#define SMEM_TOT (3 * STAGE)

// -------- scratch (device globals; no allocation allowed) --------
__device__ int g_cnt[NE], g_off[NE], g_ntile, g_tile_e[64];
__device__ int g_list[NE * T_TOK];
__device__ int g_slot[2 * T_TOK];
__device__ float g_wpair[2 * T_TOK];
__device__ __align__(256) __half g_w13[(size_t)NE * 2 * HID * DIM];  // 128MB
__device__ __align__(256) __half g_w2c[(size_t)NE * DIM * HID];      // 64MB
__device__ __align__(256) __half g_x16[(size_t)MAXMT * 128 * DIM];   // 10MB
__device__ __align__(256) __half g_h16[(size_t)MAXMT * 128 * HID];   // 40MB
__device__ __align__(256) float g_ye[(size_t)MAXMT * 128 * DIM];     // 20MB

// -------- helpers --------
__device__ __forceinline__ uint32_t s2u(const void* p) {
  uint32_t a;
  asm("{ .reg .u64 t; cvta.to.shared.u64 t, %1; cvt.u32.u64 %0, t; }" : "=r"(a) : "l"(p));
  return a;
}
__device__ __forceinline__ void cp16(uint32_t dst, const void* src) {
  asm volatile("cp.async.cg.shared.global [%0], [%1], 16;" ::"r"(dst), "l"(src));
}
__device__ __forceinline__ void cpcommit() { asm volatile("cp.async.commit_group;"); }
__device__ __forceinline__ void cpwait2() { asm volatile("cp.async.wait_group 2;"); }

__device__ __forceinline__ void ldsm4(uint32_t r[4], uint32_t a) {
  asm volatile("ldmatrix.sync.aligned.m8n8.x4.shared.b16 {%0,%1,%2,%3}, [%4];"
               : "=r"(r[0]), "=r"(r[1]), "=r"(r[2]), "=r"(r[3])
               : "r"(a));
}
__device__ __forceinline__ void mma_h(float c[4], const uint32_t a[4], uint32_t b0, uint32_t b1) {
  asm volatile(
      "mma.sync.aligned.m16n8k16.row.col.f32.f16.f16.f32 "
      "{%0,%1,%2,%3}, {%4,%5,%6,%7}, {%8,%9}, {%0,%1,%2,%3};"
      : "+f"(c[0]), "+f"(c[1]), "+f"(c[2]), "+f"(c[3])
      : "r"(a[0]), "r"(a[1]), "r"(a[2]), "r"(a[3]), "r"(b0), "r"(b1));
}
__device__ __forceinline__ uint32_t packh2(float lo, float hi) {
  uint32_t r;
  asm("cvt.rn.f16x2.f32 %0, %1, %2;" : "=r"(r) : "f"(hi), "f"(lo));
  return r;
}
__device__ __forceinline__ uint4 pack8h(const float* v) {
  return make_uint4(packh2(v[0], v[1]), packh2(v[2], v[3]), packh2(v[4], v[5]),
                    packh2(v[6], v[7]));
}

// -------- small kernels --------
__global__ void reset_kernel() {
  if (threadIdx.x < NE) g_cnt[threadIdx.x] = 0;
}

__global__ void gate_kernel(const float* __restrict__ x, const float* __restrict__ gw) {
  int t = blockIdx.x * 4 + (threadIdx.x >> 5);
  int lane = threadIdx.x & 31;
  float p[NE];
#pragma unroll
  for (int e = 0; e < NE; e++) p[e] = 0.f;
  const float* xr = x + (size_t)t * DIM;
  for (int j = lane; j < DIM; j += 32) {
    float xv = xr[j];
#pragma unroll
    for (int e = 0; e < NE; e++) p[e] += xv * gw[e * DIM + j];
  }
#pragma unroll
  for (int off = 16; off > 0; off >>= 1)
#pragma unroll
    for (int e = 0; e < NE; e++) p[e] += __shfl_xor_sync(0xffffffffu, p[e], off);
  if (lane == 0) {
    int i0 = 0;
    float v0 = p[0];
#pragma unroll
    for (int e = 1; e < NE; e++)
      if (p[e] > v0) { v0 = p[e]; i0 = e; }
    int i1 = -1;
    float v1 = -3.0e38f;
#pragma unroll
    for (int e = 0; e < NE; e++)
      if (e != i0 && p[e] > v1) { v1 = p[e]; i1 = e; }
    float e1 = expf(v1 - v0);
    float w0 = 1.f / (1.f + e1);
    int pos = atomicAdd(&g_cnt[i0], 1);
    g_list[i0 * T_TOK + pos] = t * 2;
    g_wpair[t * 2] = w0;
    pos = atomicAdd(&g_cnt[i1], 1);
    g_list[i1 * T_TOK + pos] = t * 2 + 1;
    g_wpair[t * 2 + 1] = 1.f - w0;
  }
}

__global__ void finalize_kernel() {
  if (threadIdx.x == 0) {
    int off = 0;
    for (int e = 0; e < NE; e++) {
      g_off[e] = off;
      int pc = (g_cnt[e] + 127) & ~127;
      for (int t = 0; t < (pc >> 7); t++) g_tile_e[(off >> 7) + t] = e;
      off += pc;
    }
    g_ntile = off >> 7;
  }
}

// w1/w3 -> fp16, rows interleaved: R=2n -> w1[n], R=2n+1 -> w3[n]
__global__ void w13pack_kernel(const float* __restrict__ w1, const float* __restrict__ w3) {
  int idx = blockIdx.x * 256 + threadIdx.x;
  int c = idx & 127, R = (idx >> 7) & 8191, e = idx >> 20;
  const float* src = ((R & 1) ? w3 : w1) + ((size_t)e * HID + (R >> 1)) * DIM + c * 8;
  float v[8];
  *(float4*)v = *(const float4*)src;
  *(float4*)(v + 4) = *(const float4*)(src + 4);
  *(uint4*)(g_w13 + ((size_t)e * 8192 + R) * DIM + c * 8) = pack8h(v);
}

__global__ void w2pack_kernel(const float* __restrict__ w2) {
  int idx = blockIdx.x * 256 + threadIdx.x;
  int c = idx & 511, r = (idx >> 9) & 1023, e = idx >> 19;
  const float* src = w2 + ((size_t)e * DIM + r) * HID + c * 8;
  float v[8];
  *(float4*)v = *(const float4*)src;
  *(float4*)(v + 4) = *(const float4*)(src + 4);
  *(uint4*)(g_w2c + ((size_t)e * DIM + r) * HID + c * 8) = pack8h(v);
}

// gather + pad token rows -> fp16
__global__ void xpack_kernel(const float* __restrict__ x) {
  int idx = blockIdx.x * 256 + threadIdx.x;
  int c = idx & 127, s = idx >> 7;
  int mt = s >> 7;
  if (mt >= g_ntile) return;
  int e = g_tile_e[mt];
  int li = s - g_off[e];
  int pair = (li < g_cnt[e]) ? g_list[e * T_TOK + li] : -1;
  if (c == 0 && pair >= 0) g_slot[pair] = s;
  float v[8] = {0.f, 0.f, 0.f, 0.f, 0.f, 0.f, 0.f, 0.f};
  if (pair >= 0) {
    const float* src = x + (size_t)(pair >> 1) * DIM + c * 8;
    *(float4*)v = *(const float4*)src;
    *(float4*)(v + 4) = *(const float4*)(src + 4);
  }
  *(uint4*)(g_x16 + (size_t)s * DIM + c * 8) = pack8h(v);
}

// -------- GEMM core: block 128m x 128n, BK=64, 128 thr (4 warps), warp tile 64x64 --------
__device__ __forceinline__ void issue_stage(uint32_t sbase, const __half* gA, int ldA,
                                            const __half* gB, int ldB) {
  int tid = threadIdx.x;
#pragma unroll
  for (int it = 0; it < 8; it++) {
    int sidx = it * 128 + tid;
    int row = sidx >> 3, seg = sidx & 7;
    uint32_t off = SWZ(row * 128 + seg * 16);
    cp16(sbase + off, gA + (size_t)row * ldA + seg * 8);
    cp16(sbase + 16384 + off, gB + (size_t)row * ldB + seg * 8);
  }
}

__device__ __forceinline__ void compute_stage(uint32_t sA, uint32_t sB, float acc[4][8][4],
                                              int wm, int wn, int arow, int ak, int brow,
                                              int bk) {
#pragma unroll
  for (int kc = 0; kc < 64; kc += 16) {
    uint32_t a[4][4];
#pragma unroll
    for (int mf = 0; mf < 4; mf++)
      ldsm4(a[mf], sA + SWZ((wm * 64 + mf * 16 + arow) * 128 + (kc + ak) * 2));
#pragma unroll
    for (int ng = 0; ng < 4; ng++) {
      uint32_t b[4];
      ldsm4(b, sB + SWZ((wn * 64 + ng * 16 + brow) * 128 + (kc + bk) * 2));
#pragma unroll
      for (int j2 = 0; j2 < 2; j2++)
#pragma unroll
        for (int mf = 0; mf < 4; mf++)
          mma_h(acc[mf][ng * 2 + j2], a[mf], b[2 * j2], b[2 * j2 + 1]);
    }
  }
}

// 3-stage pipeline, 2 CTAs/SM.
__device__ __forceinline__ void gemm_main(const __half* gA, int ldA, const __half* gB, int ldB,
                                          int NK, uint32_t smem, float acc[4][8][4], int wm,
                                          int wn, int arow, int ak, int brow, int bk) {
#pragma unroll
  for (int s = 0; s < 3; s++) {
    issue_stage(smem + s * STAGE, gA + s * 64, ldA, gB + s * 64, ldB);
    cpcommit();
  }
  for (int i = 0; i < NK; i++) {
    cpwait2();
    __syncthreads();
    uint32_t sb = smem + (i % 3) * STAGE;
    compute_stage(sb, sb + 16384, acc, wm, wn, arow, ak, brow, bk);
    __syncthreads();
    int j = i + 3;
    if (j < NK) issue_stage(sb, gA + (size_t)j * 64, ldA, gB + (size_t)j * 64, ldB);
    cpcommit();
  }
}

// -------- FFN1: D[128 x 128] = x_tile @ w13_tile^T, cols interleaved (w1, w3) --------
__global__ __launch_bounds__(128, 2) void ffn1_kernel() {
  int mt = blockIdx.y;
  if (mt >= g_ntile) return;
  int nt = blockIdx.x, e = g_tile_e[mt];
  extern __shared__ __align__(1024) char sm[];
  uint32_t smem = s2u(sm);
  int tid = threadIdx.x, lane = tid & 31, warp = tid >> 5;
  int wm = warp >> 1, wn = warp & 1;
  int arow = (lane & 7) + ((lane >> 3) & 1) * 8, ak = (lane >> 4) * 8;
  int brow = (lane & 7) + (lane >> 4) * 8, bk = ((lane >> 3) & 1) * 8;
  float acc[4][8][4];
#pragma unroll
  for (int a = 0; a < 4; a++)
#pragma unroll
    for (int b = 0; b < 8; b++)
#pragma unroll
      for (int c = 0; c < 4; c++) acc[a][b][c] = 0.f;

  const __half* gA = g_x16 + (size_t)mt * 128 * DIM;
  const __half* gB = g_w13 + ((size_t)e * 8192 + nt * 128) * DIM;
  gemm_main(gA, DIM, gB, DIM, DIM / 64, smem, acc, wm, wn, arow, ak, brow, bk);

  int gg = lane >> 2, q = lane & 3;
  __half* hb = g_h16 + (size_t)mt * 128 * HID + (size_t)nt * 64;
#pragma unroll
  for (int mf = 0; mf < 4; mf++)
#pragma unroll
    for (int f = 0; f < 8; f++)
#pragma unroll
      for (int half = 0; half < 2; half++) {
        int row = wm * 64 + mf * 16 + gg + half * 8;
        float a1 = acc[mf][f][half * 2 + 0];
        float a3 = acc[mf][f][half * 2 + 1];
        float h = (a1 / (1.f + expf(-a1))) * a3;
        int col = wn * 32 + f * 4 + q;
        hb[(size_t)row * HID + col] = __float2half_rn(h);
      }
}

// -------- FFN2: ye[128 x 128] = h_tile @ w2_tile^T --------
__global__ __launch_bounds__(128, 2) void ffn2_kernel() {
  int mt = blockIdx.y;
  if (mt >= g_ntile) return;
  int nt = blockIdx.x, e = g_tile_e[mt];
  extern __shared__ __align__(1024) char sm[];
  uint32_t smem = s2u(sm);
  int tid = threadIdx.x, lane = tid & 31, warp = tid >> 5;
  int wm = warp >> 1, wn = warp & 1;
  int arow = (lane & 7) + ((lane >> 3) & 1) * 8, ak = (lane >> 4) * 8;
  int brow = (lane & 7) + (lane >> 4) * 8, bk = ((lane >> 3) & 1) * 8;
  float acc[4][8][4];
#pragma unroll
  for (int a = 0; a < 4; a++)
#pragma unroll
    for (int b = 0; b < 8; b++)
#pragma unroll
      for (int c = 0; c < 4; c++) acc[a][b][c] = 0.f;

  const __half* gA = g_h16 + (size_t)mt * 128 * HID;
  const __half* gB = g_w2c + ((size_t)e * DIM + nt * 128) * HID;
  gemm_main(gA, HID, gB, HID, HID / 64, smem, acc, wm, wn, arow, ak, brow, bk);

  int gg = lane >> 2, q = lane & 3;
#pragma unroll
  for (int mf = 0; mf < 4; mf++)
#pragma unroll
    for (int f = 0; f < 8; f++)
#pragma unroll
      for (int half = 0; half < 2; half++) {
        int row = wm * 64 + mf * 16 + gg + half * 8;
        int col = nt * 128 + wn * 64 + f * 8 + 2 * q;
        *(float2*)(g_ye + (size_t)(mt * 128 + row) * DIM + col) =
            make_float2(acc[mf][f][half * 2 + 0], acc[mf][f][half * 2 + 1]);
      }
}

__global__ void combine_kernel(float* __restrict__ out) {
  int idx = blockIdx.x * 256 + threadIdx.x;
  int t = idx >> 10, d = idx & 1023;
  int s0 = g_slot[2 * t], s1 = g_slot[2 * t + 1];
  out[idx] = g_wpair[2 * t] * g_ye[(size_t)s0 * DIM + d] +
             g_wpair[2 * t + 1] * g_ye[(size_t)s1 * DIM + d];
}

// -------- launch --------
extern "C" void kernel_launch(void* const* d_in, const int* in_sizes, int n_in,
                              void* d_out, int out_size) {
  const float* x = (const float*)d_in[0];
  const float* gw = (const float*)d_in[1];
  const float* w1 = (const float*)d_in[2];
  const float* w2 = (const float*)d_in[3];
  const float* w3 = (const float*)d_in[4];
  float* out = (float*)d_out;

  cudaFuncSetAttribute(ffn1_kernel, cudaFuncAttributeMaxDynamicSharedMemorySize, SMEM_TOT);
  cudaFuncSetAttribute(ffn2_kernel, cudaFuncAttributeMaxDynamicSharedMemorySize, SMEM_TOT);

  reset_kernel<<<1, 32>>>();
  gate_kernel<<<T_TOK / 4, 128>>>(x, gw);
  finalize_kernel<<<1, 32>>>();
  w13pack_kernel<<<(NE * 8192 * 128) / 256, 256>>>(w1, w3);
  w2pack_kernel<<<(NE * 1024 * 512) / 256, 256>>>(w2);
  xpack_kernel<<<(MAXMT * 128 * 128) / 256, 256>>>(x);
  ffn1_kernel<<<dim3(64, MAXMT), 128, SMEM_TOT>>>();
  ffn2_kernel<<<dim3(8, MAXMT), 128, SMEM_TOT>>>();
  combine_kernel<<<(T_TOK * DIM) / 256, 256>>>(out);
}